// round 6
// baseline (speedup 1.0000x reference)
#include <cuda_runtime.h>

#define CIN  64
#define HH   32
#define WW   32
#define COUT 128
#define NK   9

#define XSC    307.77494205f      // PSCALE(19.235933878) * 16 entries per b2 unit
#define TBIAS  128.0f             // z = -8  ->  index 0
#define CEXP   0.26359713812f     // 2^{-s_b2}
#define OSCALE_EFF 2.7025482e-5f  // ALPHA*R*ln2^2
#define MAGIC  8388608.0f         // 2^23 round-to-nearest anchor
#define MCLAMP 8389119.0f         // MAGIC + 511

// 1024 bins = (cin, co-group-of-8). 72 sorted float2 {t'=theta*XSC-TBIAS,
// pk=(co_l<<25)|x_byte_off} ascending by theta = 36 float4. +4 global pad.
__device__ float4 g_tab[1024 * 36 + 4];

__device__ __forceinline__ float ex2a(float x) {
    float r; asm("ex2.approx.ftz.f32 %0, %1;" : "=f"(r) : "f"(x)); return r;
}
__device__ __forceinline__ float lg2a(float x) {
    float r; asm("lg2.approx.ftz.f32 %0, %1;" : "=f"(r) : "f"(x)); return r;
}

// r(z) = softplus_b2(z)^2 - softplus_b2(z-s)^2 in b2^2 units, z in [-8.1, 24.1]
__device__ __forceinline__ float rfun(float z) {
    float e  = ex2a(z);
    float l1 = lg2a(1.f + e);
    float l2 = lg2a(fmaf(e, CEXP, 1.f));
    return (l1 - l2) * (l1 + l2);
}

// ---------------- prepass: per-(cin, co-group-of-8) bitonic sort of 72 ----------------
__global__ void __launch_bounds__(128) k_sort(const float* __restrict__ theta) {
    __shared__ float sk[128];
    __shared__ unsigned sv[128];
    const int bx  = blockIdx.x;          // 1024 bins = cin*16 + grp
    const int cin = bx >> 4;
    const int grp = bx & 15;
    const int t   = threadIdx.x;

    float key = 1e30f;
    unsigned val = 0;
    if (t < 72) {
        int co_l = t / 9;                // 0..7
        int kk   = t - co_l * 9;
        int co   = grp * 8 + co_l;
        key = theta[(co * CIN + cin) * NK + kk] * XSC - TBIAS;
        // x byte offset in phase tile [16 cin][18 rows][12 stride]
        unsigned xoff = (unsigned)(((cin & 15) * 216 + (kk / 3) * 12 + (kk % 3)) * 4);
        val = ((unsigned)co_l << 25) | xoff;   // pk>>16 = co_l*512 = acc byte off
    }
    sk[t] = key; sv[t] = val;
    __syncthreads();

    for (int ksz = 2; ksz <= 128; ksz <<= 1) {
        for (int j = ksz >> 1; j > 0; j >>= 1) {
            int ixj = t ^ j;
            if (ixj > t) {
                bool up = ((t & ksz) == 0);
                float a = sk[t], b = sk[ixj];
                if (up ? (a > b) : (a < b)) {
                    unsigned va = sv[t], vb = sv[ixj];
                    sk[t] = b; sk[ixj] = a;
                    sv[t] = vb; sv[ixj] = va;
                }
            }
            __syncthreads();
        }
    }

    if (t < 72) {
        float2* dst = (float2*)g_tab;
        dst[bx * 72 + t] = make_float2(sk[t], __uint_as_float(sv[t]));
    }
}

// ---------------- main ----------------
__device__ __forceinline__ void proc_elem(float tp, float pv,
                                          const char* __restrict__ xc,
                                          const char* __restrict__ lutc,
                                          char* __restrict__ accc) {
    unsigned pk = __float_as_uint(pv);
    float xp = *(const float*)(xc + (pk & 0xffffu));   // x' (LDS, conflict-free)
    float c  = xp - tp;                                // index units; 0 <=> z=-8
    float cl = fmaxf(c, 0.f);
    float q  = cl + MAGIC;                             // round-to-nearest anchor
    float m  = fminf(q, MCLAMP);
    float fr = cl - (m - MAGIC);                       // in [-0.5,0.5]; tail: grows
    unsigned off = (__float_as_uint(m) & 0x1ffu) << 3;
    float2 lv = *(const float2*)(lutc + off);          // {value, central slope}
    float r  = fmaf(lv.y, fr, lv.x);                   // interp / exact tail extrap
    float* a = (float*)(accc + (pk >> 16));
    *a += r;
}

__global__ void __launch_bounds__(128, 10)
k_main(const float* __restrict__ x, float* __restrict__ out) {
    __shared__ float  s_ex[16 * 216];   // x' tile: [16 cin][18 rows][stride 12]
    __shared__ float  s_acc[8 * 128];   // [8 co][128 tid]
    __shared__ float2 s_lut[512];       // {r(z_i), (r(z_i+h)-r(z_i-h))/2}
    __shared__ float  s_th[4 * 16];     // [warp][cin_local]: window max of x'

    const int tid  = threadIdx.x;
    const int w    = tid >> 5;
    const int lane = tid & 31;
    const int wr   = (w >> 1) * 8;      // warp-tile row origin in block tile
    const int wc   = (w & 1) * 4;       // warp-tile col origin
    const int lr   = lane >> 2;         // 0..7
    const int lc   = lane & 3;          // 0..3
    const int bt_r = (blockIdx.x >> 2) * 16;   // block tile: 16 rows x 8 cols
    const int bt_c = (blockIdx.x & 3) * 8;
    const int b    = blockIdx.y;
    const int grp  = blockIdx.z;        // co group of 8

    #pragma unroll
    for (int c = 0; c < 8; ++c) s_acc[(c << 7) + tid] = 0.f;

    // LUT: 512 entries over z in [-8, 24), h = 1/16, central-difference slopes
    for (int i = tid; i < 512; i += 128) {
        float z  = -8.f + (float)i * 0.0625f;
        float v  = rfun(z);
        float sl = (rfun(z + 0.0625f) - rfun(z - 0.0625f)) * 0.5f;
        s_lut[i] = make_float2(v, sl);
    }

    const float* xbase = x + b * (CIN * HH * WW);
    const char*  xc    = (const char*)s_ex + ((wr + lr) * 12 + wc + lc) * 4;
    const char*  lutc  = (const char*)s_lut;
    char*        accc  = (char*)(s_acc + tid);

    #pragma unroll 1
    for (int ph = 0; ph < 4; ++ph) {
        const int cb = ph << 4;

        __syncthreads();                // prev phase readers done (also lut/acc init)
        for (int idx = tid; idx < 16 * 216; idx += 128) {
            unsigned u = (unsigned)idx;
            int cl2 = u / 216u;
            int rem = u - cl2 * 216u;
            int rr  = rem / 12u;        // 0..17  (rows bt_r-1 .. bt_r+16)
            int cc  = rem - rr * 12u;   // 0..11  (cols bt_c-1 .. bt_c+8; 10,11 pad)
            int gr  = bt_r - 1 + rr;
            int gc  = bt_c - 1 + cc;
            float v = 0.f;
            if ((unsigned)gr < HH && (unsigned)gc < WW && cc < 10)
                v = xbase[(cb + cl2) * (HH * WW) + gr * WW + gc] * XSC;
            s_ex[idx] = v;
        }
        __syncthreads();

        // per-(warp, cin) max over the warp's 10x6 window
        for (int cl2 = 0; cl2 < 16; ++cl2) {
            const float* pw = s_ex + cl2 * 216 + wr * 12 + wc;
            float m = -1e30f;
            for (int i = lane; i < 60; i += 32) {
                int rr = i / 6, cc = i - rr * 6;
                m = fmaxf(m, pw[rr * 12 + cc]);
            }
            #pragma unroll
            for (int off = 16; off; off >>= 1)
                m = fmaxf(m, __shfl_xor_sync(0xffffffffu, m, off));
            if (lane == 0) s_th[w * 16 + cl2] = m;
        }
        __syncwarp();

        // dense walk over sorted-live elements (break when t' >= window max)
        #pragma unroll 1
        for (int cl2 = 0; cl2 < 16; ++cl2) {
            const float   TH = s_th[w * 16 + cl2];
            const float4* pp = g_tab + ((cb + cl2) * 16 + grp) * 36;

            float4 A = __ldg(pp);
            float4 B = __ldg(pp + 1);
            #pragma unroll 1
            for (int i = 0; i < 36; i += 2) {
                if (A.x >= TH) break;            // warp-uniform
                float4 A2 = __ldg(pp + i + 2);   // prefetch (global pad at end)
                float4 B2 = __ldg(pp + i + 3);
                proc_elem(A.x, A.y, xc, lutc, accc);
                proc_elem(A.z, A.w, xc, lutc, accc);
                proc_elem(B.x, B.y, xc, lutc, accc);
                proc_elem(B.z, B.w, xc, lutc, accc);
                A = A2; B = B2;
            }
        }
    }

    // epilogue (own slots only; no sync needed)
    const int prow = bt_r + wr + lr;
    const int pcol = bt_c + wc + lc;
    float* op = out + ((long)b * COUT + grp * 8) * 1024 + prow * 32 + pcol;
    #pragma unroll
    for (int c = 0; c < 8; ++c) {
        float v = s_acc[(c << 7) + tid] * OSCALE_EFF;
        op[c * 1024] = fminf(fmaxf(v, 0.f), 9.f);
    }
}

extern "C" void kernel_launch(void* const* d_in, const int* in_sizes, int n_in,
                              void* d_out, int out_size) {
    const float* xin   = (const float*)d_in[0];
    const float* theta = (const float*)d_in[1];
    if (n_in >= 2 && in_sizes[0] == COUT * CIN * NK) {  // defensive swap
        const float* t = xin; xin = theta; theta = t;
    }

    k_sort<<<1024, 128>>>(theta);

    dim3 grid(8, 32, 16);   // 8 spatial tiles (16x8), 32 batch, 16 co-groups of 8
    k_main<<<grid, 128>>>(xin, (float*)d_out);
}

// round 7
// speedup vs baseline: 1.1775x; 1.1775x over previous
#include <cuda_runtime.h>

#define CIN  64
#define HH   32
#define WW   32
#define COUT 128
#define NK   9

#define XSC    307.77494205f      // PSCALE(19.235933878) * 16 idx units per b2
#define TBIAS  80.0f              // z = -5 b2  ->  index 0
#define CEXP   0.26359713812f     // 2^{-s_b2}
#define B2LIN  3.8471867757f      // 2*s_b2
#define B2SQ   3.7002114715f      // s_b2^2
#define ZTAIL  21.640425f         // 15*log2(e): exact-linear switch (b2 units)
#define OSCALE_EFF 2.7025482e-5f  // ALPHA*R*ln2^2
#define MAGIC  8388608.0f         // 2^23 round-to-nearest anchor
#define MCLAMP 8389119.0f         // MAGIC + 511

// 1024 bins = (cin, co-group-of-8). 72 sorted float2 {t'=theta*XSC-TBIAS,
// pk=(co_l<<25)|x_byte_off} ascending by theta = 36 float4. +4 global pad.
__device__ float4 g_tab[1024 * 36 + 4];

__device__ __forceinline__ float ex2a(float x) {
    float r; asm("ex2.approx.ftz.f32 %0, %1;" : "=f"(r) : "f"(x)); return r;
}
__device__ __forceinline__ float lg2a(float x) {
    float r; asm("lg2.approx.ftz.f32 %0, %1;" : "=f"(r) : "f"(x)); return r;
}

// r(z) = softplus_b2(z)^2 - softplus_b2(z-s)^2 in b2^2 units (LUT build range)
__device__ __forceinline__ float rfun(float z) {
    float e  = ex2a(z);
    float l1 = lg2a(1.f + e);
    float l2 = lg2a(fmaf(e, CEXP, 1.f));
    return (l1 - l2) * (l1 + l2);
}

// ---------------- prepass: per-(cin, co-group-of-8) bitonic sort of 72 ----------------
__global__ void __launch_bounds__(128) k_sort(const float* __restrict__ theta) {
    __shared__ float sk[128];
    __shared__ unsigned sv[128];
    const int bx  = blockIdx.x;          // 1024 bins = cin*16 + grp
    const int cin = bx >> 4;
    const int grp = bx & 15;
    const int t   = threadIdx.x;

    float key = 1e30f;
    unsigned val = 0;
    if (t < 72) {
        int co_l = t / 9;                // 0..7
        int kk   = t - co_l * 9;
        int co   = grp * 8 + co_l;
        key = theta[(co * CIN + cin) * NK + kk] * XSC - TBIAS;
        // x byte offset in phase tile [16 cin][18 rows][12 stride]
        unsigned xoff = (unsigned)(((cin & 15) * 216 + (kk / 3) * 12 + (kk % 3)) * 4);
        val = ((unsigned)co_l << 25) | xoff;   // pk>>16 = co_l*512 = acc byte off
    }
    sk[t] = key; sv[t] = val;
    __syncthreads();

    for (int ksz = 2; ksz <= 128; ksz <<= 1) {
        for (int j = ksz >> 1; j > 0; j >>= 1) {
            int ixj = t ^ j;
            if (ixj > t) {
                bool up = ((t & ksz) == 0);
                float a = sk[t], b = sk[ixj];
                if (up ? (a > b) : (a < b)) {
                    unsigned va = sv[t], vb = sv[ixj];
                    sk[t] = b; sk[ixj] = a;
                    sv[t] = vb; sv[ixj] = va;
                }
            }
            __syncthreads();
        }
    }

    if (t < 72) {
        float2* dst = (float2*)g_tab;
        dst[bx * 72 + t] = make_float2(sk[t], __uint_as_float(sv[t]));
    }
}

// ---------------- element flavors ----------------
// LUT flavor: 0 MUFU, LUT LDS.64
__device__ __forceinline__ void pe_lut(float tp, float pv,
                                       const char* __restrict__ xc,
                                       const char* __restrict__ lutc,
                                       char* __restrict__ accc) {
    unsigned pk = __float_as_uint(pv);
    float xp = *(const float*)(xc + (pk & 0xffffu));
    float c  = xp - tp;                                // index units; 0 <=> z=-5
    float cl = fmaxf(c, 0.f);
    float q  = cl + MAGIC;
    float m  = fminf(q, MCLAMP);
    float fr = cl - (m - MAGIC);                       // [-0.5,0.5]; tail: grows
    unsigned off = (__float_as_uint(m) & 0x1ffu) << 3;
    float2 lv = *(const float2*)(lutc + off);
    float r  = fmaf(lv.y, fr, lv.x);                   // interp / exact extrap
    float* a = (float*)(accc + (pk >> 16));
    *a += r;
}

// MUFU flavor: 3 MUFU, exact tail (R3-proven accuracy)
__device__ __forceinline__ void pe_mufu(float tp, float pv,
                                        const char* __restrict__ xc,
                                        char* __restrict__ accc) {
    unsigned pk = __float_as_uint(pv);
    float xp = *(const float*)(xc + (pk & 0xffffu));
    float zb = fmaf(xp - tp, 0.0625f, -5.f);           // b2 units
    float e  = ex2a(fminf(zb, ZTAIL));
    float l1 = lg2a(1.f + e);
    float l2 = lg2a(fmaf(e, CEXP, 1.f));
    float g  = (l1 - l2) * (l1 + l2);
    float r  = (zb > ZTAIL) ? fmaf(B2LIN, zb, -B2SQ) : g;
    float* a = (float*)(accc + (pk >> 16));
    *a += r;
}

__global__ void __launch_bounds__(128, 10)
k_main(const float* __restrict__ x, float* __restrict__ out) {
    __shared__ float  s_ex[16 * 216];   // x' tile: [16 cin][18 rows][stride 12]
    __shared__ float  s_acc[8 * 128];   // [8 co][128 tid]
    __shared__ float2 s_lut[512];       // {r(z_i), central-diff slope per idx}
    __shared__ float  s_th[4 * 16];     // [warp][cin_local]: window max of x'

    const int tid  = threadIdx.x;
    const int w    = tid >> 5;
    const int lane = tid & 31;
    const int wr   = (w >> 1) * 8;
    const int wc   = (w & 1) * 4;
    const int lr   = lane >> 2;
    const int lc   = lane & 3;
    const int bt_r = (blockIdx.x >> 2) * 16;
    const int bt_c = (blockIdx.x & 3) * 8;
    const int b    = blockIdx.y;
    const int grp  = blockIdx.z;

    #pragma unroll
    for (int c = 0; c < 8; ++c) s_acc[(c << 7) + tid] = 0.f;

    // LUT: 512 entries over z in [-5, 27), h = 1/16
    for (int i = tid; i < 512; i += 128) {
        float z  = -5.f + (float)i * 0.0625f;
        float v  = rfun(z);
        float sl = (rfun(z + 0.0625f) - rfun(z - 0.0625f)) * 0.5f;
        s_lut[i] = make_float2(v, sl);
    }

    const float* xbase = x + b * (CIN * HH * WW);
    const char*  xc    = (const char*)s_ex + ((wr + lr) * 12 + wc + lc) * 4;
    const char*  lutc  = (const char*)s_lut;
    char*        accc  = (char*)(s_acc + tid);

    #pragma unroll 1
    for (int ph = 0; ph < 4; ++ph) {
        const int cb = ph << 4;

        __syncthreads();
        for (int idx = tid; idx < 16 * 216; idx += 128) {
            unsigned u = (unsigned)idx;
            int cl2 = u / 216u;
            int rem = u - cl2 * 216u;
            int rr  = rem / 12u;
            int cc  = rem - rr * 12u;
            int gr  = bt_r - 1 + rr;
            int gc  = bt_c - 1 + cc;
            float v = 0.f;
            if ((unsigned)gr < HH && (unsigned)gc < WW && cc < 10)
                v = xbase[(cb + cl2) * (HH * WW) + gr * WW + gc] * XSC;
            s_ex[idx] = v;
        }
        __syncthreads();

        // per-(warp, cin) max over the warp's 10x6 window
        for (int cl2 = 0; cl2 < 16; ++cl2) {
            const float* pw = s_ex + cl2 * 216 + wr * 12 + wc;
            float m = -1e30f;
            for (int i = lane; i < 60; i += 32) {
                int rr = i / 6, cc = i - rr * 6;
                m = fmaxf(m, pw[rr * 12 + cc]);
            }
            #pragma unroll
            for (int off = 16; off; off >>= 1)
                m = fmaxf(m, __shfl_xor_sync(0xffffffffu, m, off));
            if (lane == 0) s_th[w * 16 + cl2] = m;
        }
        __syncwarp();

        // dense walk; flavor per cin: 5/8 MUFU, 3/8 LUT (pipe balancing)
        #pragma unroll 1
        for (int cl2 = 0; cl2 < 16; ++cl2) {
            const float   TH = s_th[w * 16 + cl2];
            const float4* pp = g_tab + ((cb + cl2) * 16 + grp) * 36;

            if (((cb + cl2) & 7) < 5) {
                float4 A = __ldg(pp);
                float4 B = __ldg(pp + 1);
                #pragma unroll 1
                for (int i = 0; i < 36; i += 2) {
                    if (A.x >= TH) break;            // warp-uniform
                    float4 A2 = __ldg(pp + i + 2);
                    float4 B2 = __ldg(pp + i + 3);
                    pe_mufu(A.x, A.y, xc, accc);
                    pe_mufu(A.z, A.w, xc, accc);
                    pe_mufu(B.x, B.y, xc, accc);
                    pe_mufu(B.z, B.w, xc, accc);
                    A = A2; B = B2;
                }
            } else {
                float4 A = __ldg(pp);
                float4 B = __ldg(pp + 1);
                #pragma unroll 1
                for (int i = 0; i < 36; i += 2) {
                    if (A.x >= TH) break;
                    float4 A2 = __ldg(pp + i + 2);
                    float4 B2 = __ldg(pp + i + 3);
                    pe_lut(A.x, A.y, xc, lutc, accc);
                    pe_lut(A.z, A.w, xc, lutc, accc);
                    pe_lut(B.x, B.y, xc, lutc, accc);
                    pe_lut(B.z, B.w, xc, lutc, accc);
                    A = A2; B = B2;
                }
            }
        }
    }

    // epilogue (own slots only)
    const int prow = bt_r + wr + lr;
    const int pcol = bt_c + wc + lc;
    float* op = out + ((long)b * COUT + grp * 8) * 1024 + prow * 32 + pcol;
    #pragma unroll
    for (int c = 0; c < 8; ++c) {
        float v = s_acc[(c << 7) + tid] * OSCALE_EFF;
        op[c * 1024] = fminf(fmaxf(v, 0.f), 9.f);
    }
}

extern "C" void kernel_launch(void* const* d_in, const int* in_sizes, int n_in,
                              void* d_out, int out_size) {
    const float* xin   = (const float*)d_in[0];
    const float* theta = (const float*)d_in[1];
    if (n_in >= 2 && in_sizes[0] == COUT * CIN * NK) {  // defensive swap
        const float* t = xin; xin = theta; theta = t;
    }

    k_sort<<<1024, 128>>>(theta);

    dim3 grid(8, 32, 16);   // 8 spatial tiles (16x8), 32 batch, 16 co-groups of 8
    k_main<<<grid, 128>>>(xin, (float*)d_out);
}